// round 9
// baseline (speedup 1.0000x reference)
#include <cuda_runtime.h>
#include <cuda_bf16.h>
#include <cstdint>

// Problem constants: B*C = 16, L = 128, N = 48
#define BC 16

// Scratch (device globals; allocation in kernel_launch is forbidden)
__device__ float g_bufA[(size_t)BC * 16384 * 48];
__device__ float g_bufB[(size_t)BC * 6144  * 48];
__device__ float g_bufC[(size_t)BC * 2304  * 48];

// Precomputed W fragments (mma.m16n8k16 B-operand layout), bf16 hi/lo split.
__device__ uint2 g_wfHi[6][1536];
__device__ uint2 g_wfLo[6][1536];

__device__ __forceinline__ float bf16hi(float v) {
    return __bfloat162float(__float2bfloat16_rn(v));
}
__device__ __forceinline__ uint32_t packbf2(float a, float b) {
    __nv_bfloat162 t = __floats2bfloat162_rn(a, b);
    return *reinterpret_cast<uint32_t*>(&t);
}

__device__ __forceinline__ void mma_bf16(float d[4], const uint4& a, const uint2& b) {
    asm volatile(
        "mma.sync.aligned.m16n8k16.row.col.f32.bf16.bf16.f32 "
        "{%0,%1,%2,%3}, {%4,%5,%6,%7}, {%8,%9}, {%0,%1,%2,%3};"
        : "+f"(d[0]), "+f"(d[1]), "+f"(d[2]), "+f"(d[3])
        : "r"(a.x), "r"(a.y), "r"(a.z), "r"(a.w), "r"(b.x), "r"(b.y));
}

// Build m16n8k16 B-fragment layout for all 6 weight matrices (bf16 hi/lo split).
__global__ void prep_wfrag(const float* __restrict__ W0, const float* __restrict__ W1,
                           const float* __restrict__ W2, const float* __restrict__ W3,
                           const float* __restrict__ W4, const float* __restrict__ W5)
{
    const int m = blockIdx.y;
    const float* W = (m==0)?W0:(m==1)?W1:(m==2)?W2:(m==3)?W3:(m==4)?W4:W5;
    const int M   = (m < 3) ? 48 : 128;
    const int NMT = M / 8;
    const int t = blockIdx.x * blockDim.x + threadIdx.x;   // 0..1535
    const int rem  = t % (NMT * 32);
    const int kc   = t / (NMT * 32);
    const int mt   = rem / 32;
    const int lane = rem % 32;
    const int tq = lane & 3, gid = lane >> 2;
    const int k0 = kc * 16 + 2 * tq;
    const int c  = mt * 8 + gid;
    const float w00 = W[(k0    ) * M + c], w01 = W[(k0 + 1) * M + c];
    const float w08 = W[(k0 + 8) * M + c], w09 = W[(k0 + 9) * M + c];
    const float h00 = bf16hi(w00), h01 = bf16hi(w01);
    const float h08 = bf16hi(w08), h09 = bf16hi(w09);
    g_wfHi[m][t] = make_uint2(packbf2(h00, h01), packbf2(h08, h09));
    g_wfLo[m][t] = make_uint2(packbf2(w00 - h00, w01 - h01), packbf2(w08 - h08, w09 - h09));
}

// out[b][j][m] = sum_k in[b][k][j] * W[k][m]   (bf16 2-split, 3 products, m16n8k16)
// MWARPS m-warps x JW j-groups; each warp: NSL strips x NTILE 8-wide m-tiles.
// A panel staged once in smem, fragment-ready bf16 hi/lo (one LDS.128 = one frag).
// THREE independent accumulator sets (one per split-product) -> 3*NTILE*NSL
// independent HMMA chains per warp, chain depth 1 per kc. Summed in epilogue.
template<int K, int M, int NW, int NS, int MWARPS, int NTILE, int MINB>
__global__ void __launch_bounds__(NW * 32, MINB) mma_stage(
    const float* __restrict__ in, const uint2* __restrict__ wHi,
    const uint2* __restrict__ wLo, float* __restrict__ out, int J)
{
    constexpr int KC  = K / 16;
    constexpr int NMT = M / 8;
    constexpr int BJ  = NS * 16;
    constexpr int JW  = NW / MWARPS;
    constexpr int NSL = NS / JW;

    __shared__ uint4 AsH[KC * NS * 32];
    __shared__ uint4 AsL[KC * NS * 32];

    const int tid  = threadIdx.x;
    const int lane = tid & 31, warp = tid >> 5;
    const int tq = lane & 3, gid = lane >> 2;
    const int b  = blockIdx.z;
    const int j0 = blockIdx.x * BJ;
    const int mt0 = (warp % MWARPS) * NTILE;
    const int s0  = (warp / MWARPS) * NSL;

    // ---- preload first B fragments (overlaps staging + barrier) ----
    uint2 bh[2][NTILE], bl[2][NTILE];
#pragma unroll
    for (int nt = 0; nt < NTILE; nt++) {
        bh[0][nt] = __ldg(&wHi[(mt0 + nt) * 32 + lane]);
        bl[0][nt] = __ldg(&wLo[(mt0 + nt) * 32 + lane]);
    }

    // ---- stage A panel: lane-owns-slot, bf16 hi/lo fragment layout ----
    const float* inb = in + (size_t)b * K * J + j0;
#pragma unroll
    for (int t = warp; t < KC * NS; t += NW) {
        const int kcb = t / NS, s = t % NS;
        const float* p = inb + (size_t)(kcb * 16 + 2 * tq) * J + s * 16 + gid;
        const float x00 = __ldg(p),                    y00 = __ldg(p + 8);
        const float x01 = __ldg(p + (size_t)J),        y01 = __ldg(p + (size_t)J + 8);
        const float x08 = __ldg(p + (size_t)8 * J),    y08 = __ldg(p + (size_t)8 * J + 8);
        const float x09 = __ldg(p + (size_t)9 * J),    y09 = __ldg(p + (size_t)9 * J + 8);
        const float hx00 = bf16hi(x00), hx01 = bf16hi(x01), hx08 = bf16hi(x08), hx09 = bf16hi(x09);
        const float hy00 = bf16hi(y00), hy01 = bf16hi(y01), hy08 = bf16hi(y08), hy09 = bf16hi(y09);
        AsH[t * 32 + lane] = make_uint4(packbf2(hx00, hx01), packbf2(hy00, hy01),
                                        packbf2(hx08, hx09), packbf2(hy08, hy09));
        AsL[t * 32 + lane] = make_uint4(packbf2(x00 - hx00, x01 - hx01),
                                        packbf2(y00 - hy00, y01 - hy01),
                                        packbf2(x08 - hx08, x09 - hx09),
                                        packbf2(y08 - hy08, y09 - hy09));
    }
    __syncthreads();

    // Three independent accumulator sets: 0: ah*bh, 1: al*bh, 2: ah*bl.
    float a0[NSL][NTILE][4], a1[NSL][NTILE][4], a2[NSL][NTILE][4];
#pragma unroll
    for (int sl = 0; sl < NSL; sl++)
#pragma unroll
        for (int nt = 0; nt < NTILE; nt++)
#pragma unroll
            for (int r = 0; r < 4; r++) {
                a0[sl][nt][r] = 0.0f; a1[sl][nt][r] = 0.0f; a2[sl][nt][r] = 0.0f;
            }

#pragma unroll
    for (int kc = 0; kc < KC; kc++) {
        const int cur = kc & 1, nxt = cur ^ 1;
        if (kc + 1 < KC) {
#pragma unroll
            for (int nt = 0; nt < NTILE; nt++) {
                bh[nxt][nt] = __ldg(&wHi[((kc + 1) * NMT + mt0 + nt) * 32 + lane]);
                bl[nxt][nt] = __ldg(&wLo[((kc + 1) * NMT + mt0 + nt) * 32 + lane]);
            }
        }
#pragma unroll
        for (int sl = 0; sl < NSL; sl++) {
            const uint4 ah = AsH[(kc * NS + s0 + sl) * 32 + lane];
            const uint4 al = AsL[(kc * NS + s0 + sl) * 32 + lane];
#pragma unroll
            for (int nt = 0; nt < NTILE; nt++) {
                mma_bf16(a0[sl][nt], ah, bh[cur][nt]);   // three independent chains
                mma_bf16(a1[sl][nt], al, bh[cur][nt]);
                mma_bf16(a2[sl][nt], ah, bl[cur][nt]);
            }
        }
    }

    // ---- epilogue: merge sets, write out ----
#pragma unroll
    for (int sl = 0; sl < NSL; sl++) {
        float* op = out + (size_t)b * J * M + (size_t)(j0 + (s0 + sl) * 16 + gid) * M;
#pragma unroll
        for (int nt = 0; nt < NTILE; nt++) {
            float r0 = a0[sl][nt][0] + a1[sl][nt][0] + a2[sl][nt][0];
            float r1 = a0[sl][nt][1] + a1[sl][nt][1] + a2[sl][nt][1];
            float r2 = a0[sl][nt][2] + a1[sl][nt][2] + a2[sl][nt][2];
            float r3 = a0[sl][nt][3] + a1[sl][nt][3] + a2[sl][nt][3];
            const int mc = (mt0 + nt) * 8 + 2 * tq;
            *reinterpret_cast<float2*>(&op[mc])              = make_float2(r0, r1);
            *reinterpret_cast<float2*>(&op[(size_t)8 * M + mc]) = make_float2(r2, r3);
        }
    }
}

extern "C" void kernel_launch(void* const* d_in, const int* in_sizes, int n_in,
                              void* d_out, int out_size)
{
    const float* x   = (const float*)d_in[0];
    const float* EN3 = (const float*)d_in[1];
    const float* EN2 = (const float*)d_in[2];
    const float* EN1 = (const float*)d_in[3];
    const float* DE3 = (const float*)d_in[4];
    const float* DE2 = (const float*)d_in[5];
    const float* DE1 = (const float*)d_in[6];
    float* out = (float*)d_out;

    float *bufA, *bufB, *bufC;
    cudaGetSymbolAddress((void**)&bufA, g_bufA);
    cudaGetSymbolAddress((void**)&bufB, g_bufB);
    cudaGetSymbolAddress((void**)&bufC, g_bufC);
    uint2 *wfHi, *wfLo;
    cudaGetSymbolAddress((void**)&wfHi, g_wfHi);
    cudaGetSymbolAddress((void**)&wfLo, g_wfLo);

    prep_wfrag<<<dim3(12, 6), 128>>>(EN3, EN2, EN1, DE3, DE2, DE1);

    // Encode: K=128,M=48. 4 warps = 2 m-warps(NTILE=3) x 2 j-groups(NSL=1). BJ=32.
    //   9 independent HMMA chains/warp. smem 16KB. minB=5 (~102-reg cap, no spills).
    // Decode: K=48,M=128. 8 warps = 8 m-warps(NTILE=2), NS=1 -> BJ=16.
    //   6 independent chains/warp. smem 3KB. minB=3 (~85-reg cap).
    // (single decode ordering == averaged result exactly; mode contractions commute)
    auto enc = mma_stage<128, 48, 4, 2, 2, 3, 5>;
    auto dec = mma_stage<48, 128, 8, 1, 8, 2, 3>;

    // S1: contract d.  x[bc][d][hw]   (J=16384) -> bufA = [bc][h][w][p]
    enc<<<dim3(512, 1, BC), 128>>>(x,    wfHi + 0*1536, wfLo + 0*1536, bufA, 16384);
    // S2: contract h.  bufA[bc][h][wp] (J=6144) -> bufB = [bc][w][p][q]
    enc<<<dim3(192, 1, BC), 128>>>(bufA, wfHi + 1*1536, wfLo + 1*1536, bufB, 6144);
    // S3: contract w.  bufB[bc][w][pq] (J=2304) -> bufC = enc = [bc][p][q][r]
    enc<<<dim3(72, 1, BC), 128>>>(bufB, wfHi + 2*1536, wfLo + 2*1536, bufC, 2304);

    // S4: contract p.  enc[bc][p][qr]  (J=2304) -> bufB = [bc][q][r][d]
    dec<<<dim3(144, 1, BC), 256>>>(bufC, wfHi + 3*1536, wfLo + 3*1536, bufB, 2304);
    // S5: contract q.  bufB[bc][q][rd] (J=6144) -> bufA = [bc][r][d][h]
    dec<<<dim3(384, 1, BC), 256>>>(bufB, wfHi + 4*1536, wfLo + 4*1536, bufA, 6144);
    // S6: contract r.  bufA[bc][r][dh] (J=16384) -> out = [b][c][d][h][w]
    dec<<<dim3(1024, 1, BC), 256>>>(bufA, wfHi + 5*1536, wfLo + 5*1536, out, 16384);
}

// round 10
// speedup vs baseline: 1.0916x; 1.0916x over previous
#include <cuda_runtime.h>
#include <cuda_bf16.h>
#include <cstdint>

// Problem constants: B*C = 16, L = 128, N = 48
#define BC 16

// Scratch (device globals; allocation in kernel_launch is forbidden)
__device__ float g_bufA[(size_t)BC * 16384 * 48];
__device__ float g_bufB[(size_t)BC * 6144  * 48];
__device__ float g_bufC[(size_t)BC * 2304  * 48];

// Precomputed W fragments (mma.m16n8k16 B-operand layout), bf16 hi/lo split.
__device__ uint2 g_wfHi[6][1536];
__device__ uint2 g_wfLo[6][1536];

__device__ __forceinline__ float bf16hi(float v) {
    return __bfloat162float(__float2bfloat16_rn(v));
}
__device__ __forceinline__ uint32_t packbf2(float a, float b) {
    __nv_bfloat162 t = __floats2bfloat162_rn(a, b);
    return *reinterpret_cast<uint32_t*>(&t);
}

__device__ __forceinline__ void mma_bf16(float d[4], const uint4& a, const uint2& b) {
    asm volatile(
        "mma.sync.aligned.m16n8k16.row.col.f32.bf16.bf16.f32 "
        "{%0,%1,%2,%3}, {%4,%5,%6,%7}, {%8,%9}, {%0,%1,%2,%3};"
        : "+f"(d[0]), "+f"(d[1]), "+f"(d[2]), "+f"(d[3])
        : "r"(a.x), "r"(a.y), "r"(a.z), "r"(a.w), "r"(b.x), "r"(b.y));
}

// Build m16n8k16 B-fragment layout for all 6 weight matrices (bf16 hi/lo split).
__global__ void prep_wfrag(const float* __restrict__ W0, const float* __restrict__ W1,
                           const float* __restrict__ W2, const float* __restrict__ W3,
                           const float* __restrict__ W4, const float* __restrict__ W5)
{
    const int m = blockIdx.y;
    const float* W = (m==0)?W0:(m==1)?W1:(m==2)?W2:(m==3)?W3:(m==4)?W4:W5;
    const int M   = (m < 3) ? 48 : 128;
    const int NMT = M / 8;
    const int t = blockIdx.x * blockDim.x + threadIdx.x;   // 0..1535
    const int rem  = t % (NMT * 32);
    const int kc   = t / (NMT * 32);
    const int mt   = rem / 32;
    const int lane = rem % 32;
    const int tq = lane & 3, gid = lane >> 2;
    const int k0 = kc * 16 + 2 * tq;
    const int c  = mt * 8 + gid;
    const float w00 = W[(k0    ) * M + c], w01 = W[(k0 + 1) * M + c];
    const float w08 = W[(k0 + 8) * M + c], w09 = W[(k0 + 9) * M + c];
    const float h00 = bf16hi(w00), h01 = bf16hi(w01);
    const float h08 = bf16hi(w08), h09 = bf16hi(w09);
    g_wfHi[m][t] = make_uint2(packbf2(h00, h01), packbf2(h08, h09));
    g_wfLo[m][t] = make_uint2(packbf2(w00 - h00, w01 - h01), packbf2(w08 - h08, w09 - h09));
}

// out[b][j][m] = sum_k in[b][k][j] * W[k][m]   (bf16 2-split, 3 products, m16n8k16)
// K split into NCH chunks of CH kc-steps; A panel double-buffered in smem.
// While chunk c computes, chunk c+1's LDGs sit in registers -> DRAM latency of
// all chunks except the first is hidden under HMMA work.
// Each warp owns at most one staging slot per chunk (SLOTS = CH*NS <= NW).
template<int K, int M, int NW, int NS, int MWARPS, int NTILE, int CH, int MINB>
__global__ void __launch_bounds__(NW * 32, MINB) mma_stage(
    const float* __restrict__ in, const uint2* __restrict__ wHi,
    const uint2* __restrict__ wLo, float* __restrict__ out, int J)
{
    constexpr int KC    = K / 16;
    constexpr int NCH   = KC / CH;
    constexpr int SLOTS = CH * NS;          // staging slots per chunk (<= NW)
    constexpr int NMT   = M / 8;
    constexpr int BJ    = NS * 16;
    constexpr int JW    = NW / MWARPS;
    constexpr int NSL   = NS / JW;
    static_assert(SLOTS <= NW, "one slot per warp");

    __shared__ uint4 AsH[2][SLOTS * 32];
    __shared__ uint4 AsL[2][SLOTS * 32];

    const int tid  = threadIdx.x;
    const int lane = tid & 31, warp = tid >> 5;
    const int tq = lane & 3, gid = lane >> 2;
    const int b  = blockIdx.z;
    const int j0 = blockIdx.x * BJ;
    const int mt0 = (warp % MWARPS) * NTILE;
    const int s0  = (warp / MWARPS) * NSL;
    const bool stager = (warp < SLOTS);
    const int  skc = warp / NS;            // local kc of this warp's slot
    const int  ss  = warp % NS;            // strip of this warp's slot

    const float* inb = in + (size_t)b * K * J + j0;

    // staging registers (one slot's 8 values)
    float r0, r1, r2, r3, r4, r5, r6, r7;
    if (stager) {
        const float* p = inb + (size_t)(skc * 16 + 2 * tq) * J + ss * 16 + gid;
        r0 = __ldg(p);                 r1 = __ldg(p + 8);
        r2 = __ldg(p + (size_t)J);     r3 = __ldg(p + (size_t)J + 8);
        r4 = __ldg(p + (size_t)8 * J); r5 = __ldg(p + (size_t)8 * J + 8);
        r6 = __ldg(p + (size_t)9 * J); r7 = __ldg(p + (size_t)9 * J + 8);
    }

    // B fragments: double-buffered per kc (global index)
    uint2 bh[2][NTILE], bl[2][NTILE];
#pragma unroll
    for (int nt = 0; nt < NTILE; nt++) {
        bh[0][nt] = __ldg(&wHi[(mt0 + nt) * 32 + lane]);
        bl[0][nt] = __ldg(&wLo[(mt0 + nt) * 32 + lane]);
    }

    float acc[NSL][NTILE][4];
#pragma unroll
    for (int sl = 0; sl < NSL; sl++)
#pragma unroll
        for (int nt = 0; nt < NTILE; nt++)
#pragma unroll
            for (int rr = 0; rr < 4; rr++) acc[sl][nt][rr] = 0.0f;

#pragma unroll
    for (int ch = 0; ch < NCH; ch++) {
        const int buf = ch & 1;
        // convert + store this chunk's slot
        if (stager) {
            const float h0 = bf16hi(r0), h1 = bf16hi(r1), h2 = bf16hi(r2), h3 = bf16hi(r3);
            const float h4 = bf16hi(r4), h5 = bf16hi(r5), h6 = bf16hi(r6), h7 = bf16hi(r7);
            AsH[buf][warp * 32 + lane] = make_uint4(packbf2(h0, h2), packbf2(h1, h3),
                                                    packbf2(h4, h6), packbf2(h5, h7));
            AsL[buf][warp * 32 + lane] = make_uint4(packbf2(r0 - h0, r2 - h2),
                                                    packbf2(r1 - h1, r3 - h3),
                                                    packbf2(r4 - h4, r6 - h6),
                                                    packbf2(r5 - h5, r7 - h7));
        }
        __syncthreads();
        // issue next chunk's LDGs (latency hidden under compute below)
        if (stager && ch + 1 < NCH) {
            const float* p = inb + (size_t)(((ch + 1) * CH + skc) * 16 + 2 * tq) * J
                                 + ss * 16 + gid;
            r0 = __ldg(p);                 r1 = __ldg(p + 8);
            r2 = __ldg(p + (size_t)J);     r3 = __ldg(p + (size_t)J + 8);
            r4 = __ldg(p + (size_t)8 * J); r5 = __ldg(p + (size_t)8 * J + 8);
            r6 = __ldg(p + (size_t)9 * J); r7 = __ldg(p + (size_t)9 * J + 8);
        }
        // compute this chunk
#pragma unroll
        for (int kcL = 0; kcL < CH; kcL++) {
            const int kc = ch * CH + kcL;
            const int cur = kc & 1, nxt = cur ^ 1;
            if (kc + 1 < KC) {
#pragma unroll
                for (int nt = 0; nt < NTILE; nt++) {
                    bh[nxt][nt] = __ldg(&wHi[((kc + 1) * NMT + mt0 + nt) * 32 + lane]);
                    bl[nxt][nt] = __ldg(&wLo[((kc + 1) * NMT + mt0 + nt) * 32 + lane]);
                }
            }
#pragma unroll
            for (int sl = 0; sl < NSL; sl++) {
                const uint4 ah = AsH[buf][(kcL * NS + s0 + sl) * 32 + lane];
                const uint4 al = AsL[buf][(kcL * NS + s0 + sl) * 32 + lane];
#pragma unroll
                for (int nt = 0; nt < NTILE; nt++) {
                    mma_bf16(acc[sl][nt], al, bh[cur][nt]);   // small terms first
                    mma_bf16(acc[sl][nt], ah, bl[cur][nt]);
                    mma_bf16(acc[sl][nt], ah, bh[cur][nt]);
                }
            }
        }
        // no trailing sync needed: next STS targets buf^1, whose readers
        // finished before the sync above (one-iteration separation).
    }

    // ---- write out ----
#pragma unroll
    for (int sl = 0; sl < NSL; sl++) {
        float* op = out + (size_t)b * J * M + (size_t)(j0 + (s0 + sl) * 16 + gid) * M;
#pragma unroll
        for (int nt = 0; nt < NTILE; nt++) {
            const int mc = (mt0 + nt) * 8 + 2 * tq;
            *reinterpret_cast<float2*>(&op[mc]) =
                make_float2(acc[sl][nt][0], acc[sl][nt][1]);
            *reinterpret_cast<float2*>(&op[(size_t)8 * M + mc]) =
                make_float2(acc[sl][nt][2], acc[sl][nt][3]);
        }
    }
}

extern "C" void kernel_launch(void* const* d_in, const int* in_sizes, int n_in,
                              void* d_out, int out_size)
{
    const float* x   = (const float*)d_in[0];
    const float* EN3 = (const float*)d_in[1];
    const float* EN2 = (const float*)d_in[2];
    const float* EN1 = (const float*)d_in[3];
    const float* DE3 = (const float*)d_in[4];
    const float* DE2 = (const float*)d_in[5];
    const float* DE1 = (const float*)d_in[6];
    float* out = (float*)d_out;

    float *bufA, *bufB, *bufC;
    cudaGetSymbolAddress((void**)&bufA, g_bufA);
    cudaGetSymbolAddress((void**)&bufB, g_bufB);
    cudaGetSymbolAddress((void**)&bufC, g_bufC);
    uint2 *wfHi, *wfLo;
    cudaGetSymbolAddress((void**)&wfHi, g_wfHi);
    cudaGetSymbolAddress((void**)&wfLo, g_wfLo);

    prep_wfrag<<<dim3(12, 6), 128>>>(EN3, EN2, EN1, DE3, DE2, DE1);

    // NOTE staging pack order fixed to match A-fragment (a0={k0,k0+1} row gid,
    // a1=row gid+8, a2/a3=k0+8): values r0..r7 = (x00,y00,x01,y01,x08,y08,x09,y09)
    // packed as (x00,x01),(y00,y01),(x08,x09),(y08,y09).
    // Encode: K=128 (8 kc), CH=2 -> 4 chunks, SLOTS=4=NW. BJ=32, smem 8KB. minB=8.
    // Decode: K=48 (3 kc), CH=1 -> 3 chunks, SLOTS=2<=8. BJ=32, smem 4KB. minB=4.
    // (single decode ordering == averaged result exactly; mode contractions commute)
    auto enc = mma_stage<128, 48, 4, 2, 2, 3, 2, 8>;
    auto dec = mma_stage<48, 128, 8, 2, 8, 2, 1, 4>;

    // S1: contract d.  x[bc][d][hw]   (J=16384) -> bufA = [bc][h][w][p]
    enc<<<dim3(512, 1, BC), 128>>>(x,    wfHi + 0*1536, wfLo + 0*1536, bufA, 16384);
    // S2: contract h.  bufA[bc][h][wp] (J=6144) -> bufB = [bc][w][p][q]
    enc<<<dim3(192, 1, BC), 128>>>(bufA, wfHi + 1*1536, wfLo + 1*1536, bufB, 6144);
    // S3: contract w.  bufB[bc][w][pq] (J=2304) -> bufC = enc = [bc][p][q][r]
    enc<<<dim3(72, 1, BC), 128>>>(bufB, wfHi + 2*1536, wfLo + 2*1536, bufC, 2304);

    // S4: contract p.  enc[bc][p][qr]  (J=2304) -> bufB = [bc][q][r][d]
    dec<<<dim3(72, 1, BC), 256>>>(bufC, wfHi + 3*1536, wfLo + 3*1536, bufB, 2304);
    // S5: contract q.  bufB[bc][q][rd] (J=6144) -> bufA = [bc][r][d][h]
    dec<<<dim3(192, 1, BC), 256>>>(bufB, wfHi + 4*1536, wfLo + 4*1536, bufA, 6144);
    // S6: contract r.  bufA[bc][r][dh] (J=16384) -> out = [b][c][d][h][w]
    dec<<<dim3(512, 1, BC), 256>>>(bufA, wfHi + 5*1536, wfLo + 5*1536, out, 16384);
}

// round 11
// speedup vs baseline: 1.2887x; 1.1806x over previous
#include <cuda_runtime.h>
#include <cuda_bf16.h>
#include <cstdint>

// Problem constants: B*C = 16, L = 128, N = 48
#define BC 16

// Scratch (device globals; allocation in kernel_launch is forbidden)
__device__ float g_bufA[(size_t)BC * 16384 * 48];
__device__ float g_bufB[(size_t)BC * 6144  * 48];
__device__ float g_bufC[(size_t)BC * 2304  * 48];

// Precomputed W fragments (mma.m16n8k16 B-operand layout), bf16 hi/lo split.
__device__ uint2 g_wfHi[6][1536];
__device__ uint2 g_wfLo[6][1536];

__device__ __forceinline__ float bf16hi(float v) {
    return __bfloat162float(__float2bfloat16_rn(v));
}
__device__ __forceinline__ uint32_t packbf2(float a, float b) {
    __nv_bfloat162 t = __floats2bfloat162_rn(a, b);
    return *reinterpret_cast<uint32_t*>(&t);
}

__device__ __forceinline__ void mma_bf16(float d[4], const uint4& a, const uint2& b) {
    asm volatile(
        "mma.sync.aligned.m16n8k16.row.col.f32.bf16.bf16.f32 "
        "{%0,%1,%2,%3}, {%4,%5,%6,%7}, {%8,%9}, {%0,%1,%2,%3};"
        : "+f"(d[0]), "+f"(d[1]), "+f"(d[2]), "+f"(d[3])
        : "r"(a.x), "r"(a.y), "r"(a.z), "r"(a.w), "r"(b.x), "r"(b.y));
}

// ldmatrix x4 transposed: builds m16n8k16 A-fragment from [k][j] bf16 smem.
__device__ __forceinline__ uint4 ldsm_t(uint32_t addr) {
    uint4 r;
    asm volatile(
        "ldmatrix.sync.aligned.m8n8.x4.trans.shared.b16 {%0,%1,%2,%3}, [%4];"
        : "=r"(r.x), "=r"(r.y), "=r"(r.z), "=r"(r.w) : "r"(addr));
    return r;
}

// Build m16n8k16 B-fragment layout for all 6 weight matrices (bf16 hi/lo split).
__global__ void prep_wfrag(const float* __restrict__ W0, const float* __restrict__ W1,
                           const float* __restrict__ W2, const float* __restrict__ W3,
                           const float* __restrict__ W4, const float* __restrict__ W5)
{
    const int m = blockIdx.y;
    const float* W = (m==0)?W0:(m==1)?W1:(m==2)?W2:(m==3)?W3:(m==4)?W4:W5;
    const int M   = (m < 3) ? 48 : 128;
    const int NMT = M / 8;
    const int t = blockIdx.x * blockDim.x + threadIdx.x;   // 0..1535
    const int rem  = t % (NMT * 32);
    const int kc   = t / (NMT * 32);
    const int mt   = rem / 32;
    const int lane = rem % 32;
    const int tq = lane & 3, gid = lane >> 2;
    const int k0 = kc * 16 + 2 * tq;
    const int c  = mt * 8 + gid;
    const float w00 = W[(k0    ) * M + c], w01 = W[(k0 + 1) * M + c];
    const float w08 = W[(k0 + 8) * M + c], w09 = W[(k0 + 9) * M + c];
    const float h00 = bf16hi(w00), h01 = bf16hi(w01);
    const float h08 = bf16hi(w08), h09 = bf16hi(w09);
    g_wfHi[m][t] = make_uint2(packbf2(h00, h01), packbf2(h08, h09));
    g_wfLo[m][t] = make_uint2(packbf2(w00 - h00, w01 - h01), packbf2(w08 - h08, w09 - h09));
}

// out[b][j][m] = sum_k in[b][k][j] * W[k][m]   (bf16 2-split, 3 products, m16n8k16)
// MWARPS m-warps x JW j-groups; each warp: NSL strips x NTILE 8-wide m-tiles.
// A panel staged COALESCED (LDG.128, full 128B lines) into [k][j] bf16 hi/lo
// smem (PJ=BJ+8 pad); fragments built by ldmatrix.x4.trans at use.
// kc-outer loop; B fragments (precomputed layout) double-buffered in regs.
template<int K, int M, int NW, int NS, int MWARPS, int NTILE, int MINB>
__global__ void __launch_bounds__(NW * 32, MINB) mma_stage(
    const float* __restrict__ in, const uint2* __restrict__ wHi,
    const uint2* __restrict__ wLo, float* __restrict__ out, int J)
{
    constexpr int KC  = K / 16;
    constexpr int NMT = M / 8;
    constexpr int BJ  = NS * 16;
    constexpr int PJ  = BJ + 8;            // bf16 pad: conflict-spread rows
    constexpr int JW  = NW / MWARPS;
    constexpr int NSL = NS / JW;
    constexpr int NT  = NW * 32;

    __shared__ __nv_bfloat16 AsH[K * PJ];
    __shared__ __nv_bfloat16 AsL[K * PJ];

    const int tid  = threadIdx.x;
    const int lane = tid & 31, warp = tid >> 5;
    const int tq = lane & 3, gid = lane >> 2;
    const int b  = blockIdx.z;
    const int j0 = blockIdx.x * BJ;
    const int mt0 = (warp % MWARPS) * NTILE;
    const int s0  = (warp / MWARPS) * NSL;

    // ---- preload first B fragments (overlaps staging) ----
    uint2 bh[2][NTILE], bl[2][NTILE];
#pragma unroll
    for (int nt = 0; nt < NTILE; nt++) {
        bh[0][nt] = __ldg(&wHi[(mt0 + nt) * 32 + lane]);
        bl[0][nt] = __ldg(&wLo[(mt0 + nt) * 32 + lane]);
    }

    // ---- stage A panel: coalesced float4 loads, hi/lo bf16 split, STS.64 ----
    const float* inb = in + (size_t)b * K * J + j0;
#pragma unroll
    for (int idx = tid; idx < K * BJ / 4; idx += NT) {
        const int k  = idx / (BJ / 4);
        const int jq = (idx % (BJ / 4)) * 4;
        const float4 v = *reinterpret_cast<const float4*>(&inb[(size_t)k * J + jq]);
        const uint32_t h01 = packbf2(v.x, v.y);
        const uint32_t h23 = packbf2(v.z, v.w);
        const __nv_bfloat162 hb01 = *reinterpret_cast<const __nv_bfloat162*>(&h01);
        const __nv_bfloat162 hb23 = *reinterpret_cast<const __nv_bfloat162*>(&h23);
        const uint32_t l01 = packbf2(v.x - __bfloat162float(hb01.x),
                                     v.y - __bfloat162float(hb01.y));
        const uint32_t l23 = packbf2(v.z - __bfloat162float(hb23.x),
                                     v.w - __bfloat162float(hb23.y));
        *reinterpret_cast<uint2*>(&AsH[k * PJ + jq]) = make_uint2(h01, h23);
        *reinterpret_cast<uint2*>(&AsL[k * PJ + jq]) = make_uint2(l01, l23);
    }
    __syncthreads();

    // per-lane ldmatrix base offset (bytes) within a (kc, s) tile
    const uint32_t aH0 = (uint32_t)__cvta_generic_to_shared(AsH);
    const uint32_t aL0 = (uint32_t)__cvta_generic_to_shared(AsL);
    const uint32_t lrow = ((lane & 16) >> 1) + (lane & 7);   // k row within tile
    const uint32_t lcol = (lane & 8);                        // j col within tile
    const uint32_t lofs = 2 * (lrow * PJ + lcol);

    float acc[NSL][NTILE][4];
#pragma unroll
    for (int sl = 0; sl < NSL; sl++)
#pragma unroll
        for (int nt = 0; nt < NTILE; nt++)
#pragma unroll
            for (int r = 0; r < 4; r++) acc[sl][nt][r] = 0.0f;

#pragma unroll
    for (int kc = 0; kc < KC; kc++) {
        const int cur = kc & 1, nxt = cur ^ 1;
        if (kc + 1 < KC) {
#pragma unroll
            for (int nt = 0; nt < NTILE; nt++) {
                bh[nxt][nt] = __ldg(&wHi[((kc + 1) * NMT + mt0 + nt) * 32 + lane]);
                bl[nxt][nt] = __ldg(&wLo[((kc + 1) * NMT + mt0 + nt) * 32 + lane]);
            }
        }
#pragma unroll
        for (int sl = 0; sl < NSL; sl++) {
            const uint32_t toff = 2 * (kc * 16 * PJ + (s0 + sl) * 16) + lofs;
            const uint4 ah = ldsm_t(aH0 + toff);
            const uint4 al = ldsm_t(aL0 + toff);
#pragma unroll
            for (int nt = 0; nt < NTILE; nt++) {
                mma_bf16(acc[sl][nt], al, bh[cur][nt]);   // small terms first
                mma_bf16(acc[sl][nt], ah, bl[cur][nt]);
                mma_bf16(acc[sl][nt], ah, bh[cur][nt]);
            }
        }
    }

    // ---- write out ----
#pragma unroll
    for (int sl = 0; sl < NSL; sl++) {
        float* op = out + (size_t)b * J * M + (size_t)(j0 + (s0 + sl) * 16 + gid) * M;
#pragma unroll
        for (int nt = 0; nt < NTILE; nt++) {
            const int mc = (mt0 + nt) * 8 + 2 * tq;
            *reinterpret_cast<float2*>(&op[mc]) =
                make_float2(acc[sl][nt][0], acc[sl][nt][1]);
            *reinterpret_cast<float2*>(&op[(size_t)8 * M + mc]) =
                make_float2(acc[sl][nt][2], acc[sl][nt][3]);
        }
    }
}

extern "C" void kernel_launch(void* const* d_in, const int* in_sizes, int n_in,
                              void* d_out, int out_size)
{
    const float* x   = (const float*)d_in[0];
    const float* EN3 = (const float*)d_in[1];
    const float* EN2 = (const float*)d_in[2];
    const float* EN1 = (const float*)d_in[3];
    const float* DE3 = (const float*)d_in[4];
    const float* DE2 = (const float*)d_in[5];
    const float* DE1 = (const float*)d_in[6];
    float* out = (float*)d_out;

    float *bufA, *bufB, *bufC;
    cudaGetSymbolAddress((void**)&bufA, g_bufA);
    cudaGetSymbolAddress((void**)&bufB, g_bufB);
    cudaGetSymbolAddress((void**)&bufC, g_bufC);
    uint2 *wfHi, *wfLo;
    cudaGetSymbolAddress((void**)&wfHi, g_wfHi);
    cudaGetSymbolAddress((void**)&wfLo, g_wfLo);

    prep_wfrag<<<dim3(12, 6), 128>>>(EN3, EN2, EN1, DE3, DE2, DE1);

    // Encode: K=128,M=48. 4 warps = 2 m-warps(NTILE=3) x 2 j-groups(NSL=1). BJ=32.
    //   smem 2x10.2KB bf16 panels. minB=8 -> 32 warps/SM.
    // Decode: K=48,M=128. 8 warps = 8 m-warps(NTILE=2), NSL=2. BJ=32.
    //   smem 2x3.8KB. minB=4 -> 32 warps/SM.
    // (single decode ordering == averaged result exactly; mode contractions commute)
    auto enc = mma_stage<128, 48, 4, 2, 2, 3, 8>;
    auto dec = mma_stage<48, 128, 8, 2, 8, 2, 4>;

    // S1: contract d.  x[bc][d][hw]   (J=16384) -> bufA = [bc][h][w][p]
    enc<<<dim3(512, 1, BC), 128>>>(x,    wfHi + 0*1536, wfLo + 0*1536, bufA, 16384);
    // S2: contract h.  bufA[bc][h][wp] (J=6144) -> bufB = [bc][w][p][q]
    enc<<<dim3(192, 1, BC), 128>>>(bufA, wfHi + 1*1536, wfLo + 1*1536, bufB, 6144);
    // S3: contract w.  bufB[bc][w][pq] (J=2304) -> bufC = enc = [bc][p][q][r]
    enc<<<dim3(72, 1, BC), 128>>>(bufB, wfHi + 2*1536, wfLo + 2*1536, bufC, 2304);

    // S4: contract p.  enc[bc][p][qr]  (J=2304) -> bufB = [bc][q][r][d]
    dec<<<dim3(72, 1, BC), 256>>>(bufC, wfHi + 3*1536, wfLo + 3*1536, bufB, 2304);
    // S5: contract q.  bufB[bc][q][rd] (J=6144) -> bufA = [bc][r][d][h]
    dec<<<dim3(192, 1, BC), 256>>>(bufB, wfHi + 4*1536, wfLo + 4*1536, bufA, 6144);
    // S6: contract r.  bufA[bc][r][dh] (J=16384) -> out = [b][c][d][h][w]
    dec<<<dim3(512, 1, BC), 256>>>(bufA, wfHi + 5*1536, wfLo + 5*1536, out, 16384);
}

// round 13
// speedup vs baseline: 1.3524x; 1.0494x over previous
#include <cuda_runtime.h>
#include <cuda_bf16.h>
#include <cstdint>

// Problem constants: B*C = 16, L = 128, N = 48
#define BC 16

// Scratch (device globals; allocation in kernel_launch is forbidden)
__device__ float g_bufA[(size_t)BC * 16384 * 48];
__device__ float g_bufB[(size_t)BC * 6144  * 48];
__device__ float g_bufC[(size_t)BC * 2304  * 48];

// Precomputed W fragments (mma.m16n8k16 B-operand layout), bf16 hi/lo split.
__device__ uint2 g_wfHi[6][1536];
__device__ uint2 g_wfLo[6][1536];

__device__ __forceinline__ float bf16hi(float v) {
    return __bfloat162float(__float2bfloat16_rn(v));
}
__device__ __forceinline__ uint32_t packbf2(float a, float b) {
    __nv_bfloat162 t = __floats2bfloat162_rn(a, b);
    return *reinterpret_cast<uint32_t*>(&t);
}

__device__ __forceinline__ void mma_bf16(float d[4], const uint4& a, const uint2& b) {
    asm volatile(
        "mma.sync.aligned.m16n8k16.row.col.f32.bf16.bf16.f32 "
        "{%0,%1,%2,%3}, {%4,%5,%6,%7}, {%8,%9}, {%0,%1,%2,%3};"
        : "+f"(d[0]), "+f"(d[1]), "+f"(d[2]), "+f"(d[3])
        : "r"(a.x), "r"(a.y), "r"(a.z), "r"(a.w), "r"(b.x), "r"(b.y));
}

// ldmatrix x4 transposed: builds m16n8k16 A-fragment from [k][j] bf16 smem.
__device__ __forceinline__ uint4 ldsm_t(uint32_t addr) {
    uint4 r;
    asm volatile(
        "ldmatrix.sync.aligned.m8n8.x4.trans.shared.b16 {%0,%1,%2,%3}, [%4];"
        : "=r"(r.x), "=r"(r.y), "=r"(r.z), "=r"(r.w) : "r"(addr));
    return r;
}

// Build m16n8k16 B-fragment layout for all 6 weight matrices (bf16 hi/lo split).
__global__ void prep_wfrag(const float* __restrict__ W0, const float* __restrict__ W1,
                           const float* __restrict__ W2, const float* __restrict__ W3,
                           const float* __restrict__ W4, const float* __restrict__ W5)
{
    const int m = blockIdx.y;
    const float* W = (m==0)?W0:(m==1)?W1:(m==2)?W2:(m==3)?W3:(m==4)?W4:W5;
    const int M   = (m < 3) ? 48 : 128;
    const int NMT = M / 8;
    const int t = blockIdx.x * blockDim.x + threadIdx.x;   // 0..1535
    const int rem  = t % (NMT * 32);
    const int kc   = t / (NMT * 32);
    const int mt   = rem / 32;
    const int lane = rem % 32;
    const int tq = lane & 3, gid = lane >> 2;
    const int k0 = kc * 16 + 2 * tq;
    const int c  = mt * 8 + gid;
    const float w00 = W[(k0    ) * M + c], w01 = W[(k0 + 1) * M + c];
    const float w08 = W[(k0 + 8) * M + c], w09 = W[(k0 + 9) * M + c];
    const float h00 = bf16hi(w00), h01 = bf16hi(w01);
    const float h08 = bf16hi(w08), h09 = bf16hi(w09);
    g_wfHi[m][t] = make_uint2(packbf2(h00, h01), packbf2(h08, h09));
    g_wfLo[m][t] = make_uint2(packbf2(w00 - h00, w01 - h01), packbf2(w08 - h08, w09 - h09));
}

// out[b][j][m] = sum_k in[b][k][j] * W[k][m]   (bf16 2-split, 3 products, m16n8k16)
// MWARPS m-warps x JW j-groups; each warp: NSL strips x NTILE 8-wide m-tiles.
// A panel staged COALESCED (LDG.128) into [k][j] bf16 hi/lo smem (PJ pad);
// fragments built by ldmatrix.x4.trans at use. B fragments (precomputed
// layout) double-buffered in regs, reused across NSL strips.
template<int K, int M, int NW, int NS, int MWARPS, int NTILE, int MINB>
__global__ void __launch_bounds__(NW * 32, MINB) mma_stage(
    const float* __restrict__ in, const uint2* __restrict__ wHi,
    const uint2* __restrict__ wLo, float* __restrict__ out, int J)
{
    constexpr int KC  = K / 16;
    constexpr int NMT = M / 8;
    constexpr int BJ  = NS * 16;
    constexpr int PJ  = BJ + 8;            // bf16 pad: conflict-spread rows
    constexpr int JW  = NW / MWARPS;
    constexpr int NSL = NS / JW;
    constexpr int NT  = NW * 32;

    __shared__ __nv_bfloat16 AsH[K * PJ];
    __shared__ __nv_bfloat16 AsL[K * PJ];

    const int tid  = threadIdx.x;
    const int lane = tid & 31, warp = tid >> 5;
    const int tq = lane & 3, gid = lane >> 2;
    const int b  = blockIdx.z;
    const int j0 = blockIdx.x * BJ;
    const int mt0 = (warp % MWARPS) * NTILE;
    const int s0  = (warp / MWARPS) * NSL;

    // ---- preload first B fragments (overlaps staging) ----
    uint2 bh[2][NTILE], bl[2][NTILE];
#pragma unroll
    for (int nt = 0; nt < NTILE; nt++) {
        bh[0][nt] = __ldg(&wHi[(mt0 + nt) * 32 + lane]);
        bl[0][nt] = __ldg(&wLo[(mt0 + nt) * 32 + lane]);
    }

    // ---- stage A panel: coalesced float4 loads, hi/lo bf16 split, STS.64 ----
    const float* inb = in + (size_t)b * K * J + j0;
#pragma unroll
    for (int idx = tid; idx < K * BJ / 4; idx += NT) {
        const int k  = idx / (BJ / 4);
        const int jq = (idx % (BJ / 4)) * 4;
        const float4 v = *reinterpret_cast<const float4*>(&inb[(size_t)k * J + jq]);
        const uint32_t h01 = packbf2(v.x, v.y);
        const uint32_t h23 = packbf2(v.z, v.w);
        const __nv_bfloat162 hb01 = *reinterpret_cast<const __nv_bfloat162*>(&h01);
        const __nv_bfloat162 hb23 = *reinterpret_cast<const __nv_bfloat162*>(&h23);
        const uint32_t l01 = packbf2(v.x - __bfloat162float(hb01.x),
                                     v.y - __bfloat162float(hb01.y));
        const uint32_t l23 = packbf2(v.z - __bfloat162float(hb23.x),
                                     v.w - __bfloat162float(hb23.y));
        *reinterpret_cast<uint2*>(&AsH[k * PJ + jq]) = make_uint2(h01, h23);
        *reinterpret_cast<uint2*>(&AsL[k * PJ + jq]) = make_uint2(l01, l23);
    }
    __syncthreads();

    // per-lane ldmatrix base offset (bytes) within a (kc, s) tile
    const uint32_t aH0 = (uint32_t)__cvta_generic_to_shared(AsH);
    const uint32_t aL0 = (uint32_t)__cvta_generic_to_shared(AsL);
    const uint32_t lrow = ((lane & 16) >> 1) + (lane & 7);   // k row within tile
    const uint32_t lcol = (lane & 8);                        // j col within tile
    const uint32_t lofs = 2 * (lrow * PJ + lcol);

    float acc[NSL][NTILE][4];
#pragma unroll
    for (int sl = 0; sl < NSL; sl++)
#pragma unroll
        for (int nt = 0; nt < NTILE; nt++)
#pragma unroll
            for (int r = 0; r < 4; r++) acc[sl][nt][r] = 0.0f;

#pragma unroll
    for (int kc = 0; kc < KC; kc++) {
        const int cur = kc & 1, nxt = cur ^ 1;
        if (kc + 1 < KC) {
#pragma unroll
            for (int nt = 0; nt < NTILE; nt++) {
                bh[nxt][nt] = __ldg(&wHi[((kc + 1) * NMT + mt0 + nt) * 32 + lane]);
                bl[nxt][nt] = __ldg(&wLo[((kc + 1) * NMT + mt0 + nt) * 32 + lane]);
            }
        }
#pragma unroll
        for (int sl = 0; sl < NSL; sl++) {
            const uint32_t toff = 2 * (kc * 16 * PJ + (s0 + sl) * 16) + lofs;
            const uint4 ah = ldsm_t(aH0 + toff);
            const uint4 al = ldsm_t(aL0 + toff);
#pragma unroll
            for (int nt = 0; nt < NTILE; nt++) {
                mma_bf16(acc[sl][nt], al, bh[cur][nt]);   // small terms first
                mma_bf16(acc[sl][nt], ah, bl[cur][nt]);
                mma_bf16(acc[sl][nt], ah, bh[cur][nt]);
            }
        }
    }

    // ---- write out ----
#pragma unroll
    for (int sl = 0; sl < NSL; sl++) {
        float* op = out + (size_t)b * J * M + (size_t)(j0 + (s0 + sl) * 16 + gid) * M;
#pragma unroll
        for (int nt = 0; nt < NTILE; nt++) {
            const int mc = (mt0 + nt) * 8 + 2 * tq;
            *reinterpret_cast<float2*>(&op[mc]) =
                make_float2(acc[sl][nt][0], acc[sl][nt][1]);
            *reinterpret_cast<float2*>(&op[(size_t)8 * M + mc]) =
                make_float2(acc[sl][nt][2], acc[sl][nt][3]);
        }
    }
}

extern "C" void kernel_launch(void* const* d_in, const int* in_sizes, int n_in,
                              void* d_out, int out_size)
{
    const float* x   = (const float*)d_in[0];
    const float* EN3 = (const float*)d_in[1];
    const float* EN2 = (const float*)d_in[2];
    const float* EN1 = (const float*)d_in[3];
    const float* DE3 = (const float*)d_in[4];
    const float* DE2 = (const float*)d_in[5];
    const float* DE1 = (const float*)d_in[6];
    float* out = (float*)d_out;

    float *bufA, *bufB, *bufC;
    cudaGetSymbolAddress((void**)&bufA, g_bufA);
    cudaGetSymbolAddress((void**)&bufB, g_bufB);
    cudaGetSymbolAddress((void**)&bufC, g_bufC);
    uint2 *wfHi, *wfLo;
    cudaGetSymbolAddress((void**)&wfHi, g_wfHi);
    cudaGetSymbolAddress((void**)&wfLo, g_wfLo);

    prep_wfrag<<<dim3(12, 6), 128>>>(EN3, EN2, EN1, DE3, DE2, DE1);

    // Encode: K=128,M=48. 4 warps = 2 m-warps(NTILE=3) x 2 j-groups(NSL=2). BJ=64.
    //   0.55 mem-instr/HMMA. smem 2x18.4KB. minB=6.
    // Decode: K=48,M=128. 8 warps = 8 m-warps(NTILE=2), NSL=4. BJ=64.
    //   0.5 mem-instr/HMMA. smem 2x6.9KB. minB=3.
    // (single decode ordering == averaged result exactly; mode contractions commute)
    auto enc = mma_stage<128, 48, 4, 4, 2, 3, 6>;
    auto dec = mma_stage<48, 128, 8, 4, 8, 2, 3>;

    // S1: contract d.  x[bc][d][hw]   (J=16384) -> bufA = [bc][h][w][p]
    enc<<<dim3(256, 1, BC), 128>>>(x,    wfHi + 0*1536, wfLo + 0*1536, bufA, 16384);
    // S2: contract h.  bufA[bc][h][wp] (J=6144) -> bufB = [bc][w][p][q]
    enc<<<dim3(96, 1, BC), 128>>>(bufA, wfHi + 1*1536, wfLo + 1*1536, bufB, 6144);
    // S3: contract w.  bufB[bc][w][pq] (J=2304) -> bufC = enc = [bc][p][q][r]
    enc<<<dim3(36, 1, BC), 128>>>(bufB, wfHi + 2*1536, wfLo + 2*1536, bufC, 2304);

    // S4: contract p.  enc[bc][p][qr]  (J=2304) -> bufB = [bc][q][r][d]
    dec<<<dim3(36, 1, BC), 256>>>(bufC, wfHi + 3*1536, wfLo + 3*1536, bufB, 2304);
    // S5: contract q.  bufB[bc][q][rd] (J=6144) -> bufA = [bc][r][d][h]
    dec<<<dim3(96, 1, BC), 256>>>(bufB, wfHi + 4*1536, wfLo + 4*1536, bufA, 6144);
    // S6: contract r.  bufA[bc][r][dh] (J=16384) -> out = [b][c][d][h][w]
    dec<<<dim3(256, 1, BC), 256>>>(bufA, wfHi + 5*1536, wfLo + 5*1536, out, 16384);
}